// round 7
// baseline (speedup 1.0000x reference)
#include <cuda_runtime.h>
#include <cstdint>

#define BB 8
#define NN 128
#define KK 16
#define NB (BB*NN)
#define JSPLIT 16
#define JCHUNK (NN/JSPLIT)   // 8
#define RPB 16               // rows per block in pairA

#define ALPHA_C 0.01f
#define LAM_C   1.0f
#define KAPPA_C 1.0f
#define EPSV    1e-6f

// scratch (device globals: no allocation allowed)
__device__ float g_E[NB * 256];          // E[bn] = expm(phi.G), row-major
__device__ float g_M[NB * 256];          // M[bn] = F diag(1/(sq+eps)) F^T (symmetric)
__device__ float g_w[NB * KK];           // w = F mu_q
__device__ float g_u[NB * KK];           // u = M w
__device__ float g_s1[JSPLIT * NB * KK];
__device__ float g_s2[JSPLIT * NB * KK];
__device__ float g_s3[JSPLIT * NB];

// ---------------------------------------------------------------------------
// Warp 16x16 matmul, B operand in smem. Layout: lane = 2*i + jh (i = row,
// jh = col half); lane holds 8 floats = row i, cols [jh*8, jh*8+8).
// C = T * Bs.  Bs reads are 2-address broadcasts (conflict-free).
// ---------------------------------------------------------------------------
__device__ __forceinline__ void wmm_s(const float* T, const float* __restrict__ Bs,
                                      float* C, int jh)
{
    float trow[16];
    #pragma unroll
    for (int m = 0; m < 8; m++) {
        const float other = __shfl_xor_sync(0xffffffffu, T[m], 1);
        trow[jh*8 + m]       = T[m];
        trow[(1 - jh)*8 + m] = other;
    }
    float c0=0.f,c1=0.f,c2=0.f,c3=0.f,c4=0.f,c5=0.f,c6=0.f,c7=0.f;
    #pragma unroll
    for (int l = 0; l < 16; l++) {
        const float4 b0 = *reinterpret_cast<const float4*>(Bs + l*16 + jh*8);
        const float4 b1 = *reinterpret_cast<const float4*>(Bs + l*16 + jh*8 + 4);
        const float t = trow[l];
        c0 = fmaf(t, b0.x, c0); c1 = fmaf(t, b0.y, c1);
        c2 = fmaf(t, b0.z, c2); c3 = fmaf(t, b0.w, c3);
        c4 = fmaf(t, b1.x, c4); c5 = fmaf(t, b1.y, c5);
        c6 = fmaf(t, b1.z, c6); c7 = fmaf(t, b1.w, c7);
    }
    C[0]=c0; C[1]=c1; C[2]=c2; C[3]=c3; C[4]=c4; C[5]=c5; C[6]=c6; C[7]=c7;
}

// store this lane's 8 elements into the warp buffer (then barrier)
__device__ __forceinline__ void wstore(float* Bs, const float* R, int i, int jh)
{
    __syncwarp();   // all prior reads of Bs complete
    *reinterpret_cast<float4*>(Bs + i*16 + jh*8)     = make_float4(R[0],R[1],R[2],R[3]);
    *reinterpret_cast<float4*>(Bs + i*16 + jh*8 + 4) = make_float4(R[4],R[5],R[6],R[7]);
    __syncwarp();   // writes visible before next reads
}

// ---------------------------------------------------------------------------
// Kernel 1: warp-per-matrix expm (Paterson-Stockmeyer Taylor-13 + scaling/
// squaring), smem-B matmuls. Block = 64 threads = 2 warps = 2 matrices.
// ---------------------------------------------------------------------------
__global__ void __launch_bounds__(64) prep_kernel(
    const float* __restrict__ mu_q,
    const float* __restrict__ sigma_q,
    const float* __restrict__ sigma_p,
    const float* __restrict__ phi,
    const float* __restrict__ gen,
    float* __restrict__ out_sigma)
{
    const int wid  = threadIdx.x >> 5;
    const int lane = threadIdx.x & 31;
    const int i    = lane >> 1;
    const int jh   = lane & 1;
    const int bn   = blockIdx.x * 2 + wid;

    __shared__ float sBuf[2][2][256];   // [warp][buffer][16x16]
    __shared__ float sAux[2][48];       // [warp]: r[16], mu[16], r*mu[16]
    float* buf0 = sBuf[wid][0];
    float* buf1 = sBuf[wid][1];
    float* sr   = sAux[wid];
    float* smu  = sAux[wid] + 16;
    float* srm  = sAux[wid] + 32;

    // ---- A = phi . G ----
    const float p0 = __ldg(&phi[bn*3 + 0]);
    const float p1 = __ldg(&phi[bn*3 + 1]);
    const float p2 = __ldg(&phi[bn*3 + 2]);

    float A[8];
    {
        const int base = i*16 + jh*8;
        #pragma unroll
        for (int m = 0; m < 8; m++)
            A[m] = p0*__ldg(&gen[base + m]) + p1*__ldg(&gen[256 + base + m])
                 + p2*__ldg(&gen[512 + base + m]);
    }

    if (lane < 16) {
        const float mu = mu_q[bn*KK + lane];
        const float sq = fmaxf(sigma_q[bn*KK + lane], EPSV);
        const float sp = fmaxf(sigma_p[bn*KK + lane], EPSV);
        const float r  = 1.0f / (sq + EPSV);
        sr[lane]  = r;
        smu[lane] = mu;
        srm[lane] = r * mu;
        out_sigma[bn*KK + lane] = ALPHA_C * 0.5f * (1.0f/sp - 1.0f/sq);
    }

    // ---- inf-norm & scaling ----
    float s = 0.f;
    #pragma unroll
    for (int m = 0; m < 8; m++) s += fabsf(A[m]);
    s += __shfl_xor_sync(0xffffffffu, s, 1);
    s = fmaxf(s, __shfl_xor_sync(0xffffffffu, s, 2));
    s = fmaxf(s, __shfl_xor_sync(0xffffffffu, s, 4));
    s = fmaxf(s, __shfl_xor_sync(0xffffffffu, s, 8));
    s = fmaxf(s, __shfl_xor_sync(0xffffffffu, s, 16));

    int sc = 0;
    while (s > 2.0f && sc < 24) { s *= 0.5f; sc++; }
    const float scale = ldexpf(1.0f, -sc);
    #pragma unroll
    for (int m = 0; m < 8; m++) A[m] *= scale;

    const bool hasdiag = ((i >> 3) == jh);
    const int  dm      = i & 7;

    // ---- powers: X = A^2, X2 = A^4, X3 = A^6 ----
    float X[8], X2[8], X3[8], T[8], P[8], Q[8];
    wstore(buf0, A, i, jh);
    wmm_s(A,  buf0, X,  jh);
    wstore(buf0, X, i, jh);
    wmm_s(X,  buf0, X2, jh);       // X2 = X * X
    wmm_s(X2, buf0, X3, jh);       // X3 = X2 * X  (buf0 still holds X)

    // Taylor-13 even/odd (Paterson-Stockmeyer)
    const float c1c = 1.f/2.f,     c2c = 1.f/24.f,      c3c = 1.f/720.f;
    const float c4c = 1.f/40320.f, c5c = 1.f/3628800.f, c6c = 1.f/479001600.f;
    const float d1c = 1.f/6.f,     d2c = 1.f/120.f,     d3c = 1.f/5040.f;
    const float d4c = 1.f/362880.f,d5c = 1.f/39916800.f,d6c = 1.6059044e-10f; // 1/13!

    #pragma unroll
    for (int m = 0; m < 8; m++) T[m] = fmaf(c4c, X[m], fmaf(c5c, X2[m], c6c * X3[m]));
    wstore(buf1, T, i, jh);
    wmm_s(X3, buf1, T, jh);
    #pragma unroll
    for (int m = 0; m < 8; m++)
        P[m] = fmaf(c1c, X[m], fmaf(c2c, X2[m], fmaf(c3c, X3[m], T[m])));
    if (hasdiag) P[dm] += 1.0f;

    #pragma unroll
    for (int m = 0; m < 8; m++) T[m] = fmaf(d4c, X[m], fmaf(d5c, X2[m], d6c * X3[m]));
    wstore(buf1, T, i, jh);
    wmm_s(X3, buf1, T, jh);
    #pragma unroll
    for (int m = 0; m < 8; m++)
        Q[m] = fmaf(d1c, X[m], fmaf(d2c, X2[m], fmaf(d3c, X3[m], T[m])));
    if (hasdiag) Q[dm] += 1.0f;

    // R = P + A*Q
    float R[8];
    wstore(buf1, Q, i, jh);
    wmm_s(A, buf1, R, jh);
    #pragma unroll
    for (int m = 0; m < 8; m++) R[m] += P[m];

    // squarings
    for (int q = 0; q < sc; q++) {
        wstore(buf1, R, i, jh);
        wmm_s(R, buf1, R, jh);
    }

    // ---- write E; stage in buf0 for transposed access ----
    {
        float4* eg = reinterpret_cast<float4*>(g_E + (size_t)bn*256 + i*16 + jh*8);
        eg[0] = make_float4(R[0], R[1], R[2], R[3]);
        eg[1] = make_float4(R[4], R[5], R[6], R[7]);
    }
    wstore(buf0, R, i, jh);
    const float* sE = buf0;

    // ---- M[i][j] = sum_l E[l][i] r[l] E[l][j]  (symmetric) ----
    {
        float a0=0.f,a1=0.f,a2=0.f,a3=0.f,a4=0.f,a5=0.f,a6=0.f,a7=0.f;
        #pragma unroll
        for (int l = 0; l < 16; l++) {
            const float eli_r = sE[l*16 + i] * sr[l];
            const float4 e0 = *reinterpret_cast<const float4*>(sE + l*16 + jh*8);
            const float4 e1 = *reinterpret_cast<const float4*>(sE + l*16 + jh*8 + 4);
            a0 = fmaf(eli_r, e0.x, a0); a1 = fmaf(eli_r, e0.y, a1);
            a2 = fmaf(eli_r, e0.z, a2); a3 = fmaf(eli_r, e0.w, a3);
            a4 = fmaf(eli_r, e1.x, a4); a5 = fmaf(eli_r, e1.y, a5);
            a6 = fmaf(eli_r, e1.z, a6); a7 = fmaf(eli_r, e1.w, a7);
        }
        float4* mg = reinterpret_cast<float4*>(g_M + (size_t)bn*256 + i*16 + jh*8);
        mg[0] = make_float4(a0, a1, a2, a3);
        mg[1] = make_float4(a4, a5, a6, a7);
    }

    // ---- w[k] = sum_l E[l][k] mu[l];  u[k] = sum_l E[l][k] r[l] mu[l] ----
    if (lane < 16) {
        float wacc = 0.f, uacc = 0.f;
        #pragma unroll
        for (int l = 0; l < 16; l++) {
            const float e = sE[l*16 + lane];
            wacc = fmaf(e, smu[l], wacc);
            uacc = fmaf(e, srm[l], uacc);
        }
        g_w[bn*KK + lane] = wacc;
        g_u[bn*KK + lane] = uacc;
    }
}

// ---------------------------------------------------------------------------
// Kernel 2 (phase A): partial j-sums. Grid (JSPLIT, NB/RPB), 256 threads =
// 16 groups of 16 lanes (one row each); 16 rows share the staged chunk.
// ---------------------------------------------------------------------------
__global__ void __launch_bounds__(256) pairA_kernel(
    const float* __restrict__ beta)
{
    __shared__ float sM[JCHUNK * 256];   // 8 KB
    __shared__ float swv[JCHUNK * 16];
    __shared__ float suv[JCHUNK * 16];

    const int tid   = threadIdx.x;
    const int g     = tid >> 4;
    const int lane  = tid & 15;
    const int split = blockIdx.x;
    const int bn    = blockIdx.y * RPB + g;
    const int b     = bn >> 7;
    const int irow  = bn & 127;
    const int j0    = split * JCHUNK;

    {
        const float4* src = reinterpret_cast<const float4*>(g_M + (size_t)(b*NN + j0) * 256);
        float4* dst = reinterpret_cast<float4*>(sM);
        #pragma unroll
        for (int q = 0; q < 2; q++) dst[q*256 + tid] = src[q*256 + tid];
        if (tid < JCHUNK*16) {
            swv[tid] = g_w[(size_t)(b*NN + j0) * KK + tid];
            suv[tid] = g_u[(size_t)(b*NN + j0) * KK + tid];
        }
    }

    float wir[16];
    {
        const float4* wp = reinterpret_cast<const float4*>(g_w + (size_t)bn * KK);
        #pragma unroll
        for (int q = 0; q < 4; q++) {
            const float4 v4 = wp[q];
            wir[q*4+0] = v4.x; wir[q*4+1] = v4.y; wir[q*4+2] = v4.z; wir[q*4+3] = v4.w;
        }
    }
    const float wi_self = g_w[(size_t)bn*KK + lane];
    const float* __restrict__ betarow = beta + (size_t)(b*NN + irow) * NN + j0;

    __syncthreads();

    float s1 = 0.f, s2 = 0.f, s3 = 0.f;

    #pragma unroll
    for (int jj = 0; jj < JCHUNK; jj++) {
        const float* __restrict__ Mc = sM + jj*256;   // symmetric
        float z0 = 0.f, z1 = 0.f;
        #pragma unroll
        for (int l = 0; l < 16; l += 2) {
            z0 = fmaf(Mc[ l     *16 + lane], wir[l    ], z0);
            z1 = fmaf(Mc[(l + 1)*16 + lane], wir[l + 1], z1);
        }
        const float y = (z0 + z1) - suv[jj*16 + lane];
        const float d = wi_self   - swv[jj*16 + lane];

        float tt = d * y;
        tt += __shfl_xor_sync(0xffffffffu, tt, 1);
        tt += __shfl_xor_sync(0xffffffffu, tt, 2);
        tt += __shfl_xor_sync(0xffffffffu, tt, 4);
        tt += __shfl_xor_sync(0xffffffffu, tt, 8);
        const float kl  = 0.5f * tt;
        const float bij = __ldg(betarow + jj);
        const float klb = kl * bij;

        s1 = fmaf(bij, y, s1);
        s2 = fmaf(klb, y, s2);
        s3 += klb;
    }

    const int idx = split * (NB*KK) + bn*KK + lane;
    g_s1[idx] = s1;
    g_s2[idx] = s2;
    if (lane == 0) g_s3[split * NB + bn] = s3;
}

// ---------------------------------------------------------------------------
// Kernel 3: combine splits, rotate by E_i, add self term.
// ---------------------------------------------------------------------------
__global__ void __launch_bounds__(256) finish_kernel(
    const float* __restrict__ mu_q,
    const float* __restrict__ mu_p,
    const float* __restrict__ sigma_p,
    float* __restrict__ out_mu)
{
    const int tid  = threadIdx.x;
    const int g    = tid >> 4;
    const int lane = tid & 15;
    const int bn   = blockIdx.x * 16 + g;

    float s1 = 0.f, s2 = 0.f, s3 = 0.f;
    #pragma unroll
    for (int s = 0; s < JSPLIT; s++) {
        s1 += g_s1[s*(NB*KK) + bn*KK + lane];
        s2 += g_s2[s*(NB*KK) + bn*KK + lane];
        s3 += g_s3[s*NB + bn];
    }
    const float v = LAM_C * s1 + (LAM_C / KAPPA_C) * (s2 - s3 * s1);

    float er[16];
    {
        const float4* ep = reinterpret_cast<const float4*>(g_E + (size_t)bn*256 + lane*16);
        #pragma unroll
        for (int q = 0; q < 4; q++) {
            const float4 t4 = ep[q];
            er[q*4+0] = t4.x; er[q*4+1] = t4.y; er[q*4+2] = t4.z; er[q*4+3] = t4.w;
        }
    }
    float o = 0.f;
    #pragma unroll
    for (int l = 0; l < 16; l++)
        o = fmaf(er[l], __shfl_sync(0xffffffffu, v, l, 16), o);

    const float sp   = fmaxf(sigma_p[bn*KK + lane], EPSV);
    const float self = ALPHA_C * (mu_q[bn*KK + lane] - mu_p[bn*KK + lane]) / sp;

    out_mu[bn*KK + lane] = self + o;
}

// ---------------------------------------------------------------------------
extern "C" void kernel_launch(void* const* d_in, const int* in_sizes, int n_in,
                              void* d_out, int out_size)
{
    const float* mu_q    = (const float*)d_in[0];
    const float* sigma_q = (const float*)d_in[1];
    const float* mu_p    = (const float*)d_in[2];
    const float* sigma_p = (const float*)d_in[3];
    const float* beta    = (const float*)d_in[4];
    const float* phi     = (const float*)d_in[5];
    const float* gen     = (const float*)d_in[6];

    float* out       = (float*)d_out;
    float* out_mu    = out;            // (B,N,K)
    float* out_sigma = out + NB*KK;    // (B,N,K)

    prep_kernel<<<NB/2, 64>>>(mu_q, sigma_q, sigma_p, phi, gen, out_sigma);
    pairA_kernel<<<dim3(JSPLIT, NB/RPB), 256>>>(beta);
    finish_kernel<<<NB/16, 256>>>(mu_q, mu_p, sigma_p, out_mu);
}

// round 9
// speedup vs baseline: 1.3034x; 1.3034x over previous
#include <cuda_runtime.h>
#include <cstdint>

#define BB 8
#define NN 128
#define KK 16
#define NB (BB*NN)
#define JSPLIT 8
#define JCHUNK (NN/JSPLIT)   // 16
#define RPB 16               // rows per block in pairA

#define ALPHA_C 0.01f
#define LAM_C   1.0f
#define KAPPA_C 1.0f
#define EPSV    1e-6f

// scratch (device globals: no allocation allowed)
__device__ float g_E[NB * 256];          // E[bn] = expm(phi.G), row-major
__device__ float g_M[NB * 256];          // M[bn] = F diag(1/(sq+eps)) F^T (symmetric)
__device__ float g_w[NB * KK];           // w = F mu_q
__device__ float g_u[NB * KK];           // u = M w
__device__ float g_s1[JSPLIT * NB * KK];
__device__ float g_s2[JSPLIT * NB * KK];
__device__ float g_s3[JSPLIT * NB];

// named barrier over the 64 threads (2 warps) of one matrix
__device__ __forceinline__ void mbar(int mid) {
    asm volatile("bar.sync %0, 64;" :: "r"(mid + 1) : "memory");
}

// 16x16 matmul, 4 elements per thread (row i, cols jq*4..jq*4+3).
// T rows and B columns both read from smem; all accesses conflict-free.
__device__ __forceinline__ float4 mm4(const float* __restrict__ Ts,
                                      const float* __restrict__ Bs,
                                      int i, int jq)
{
    float c0 = 0.f, c1 = 0.f, c2 = 0.f, c3 = 0.f;
    #pragma unroll
    for (int l = 0; l < 16; l++) {
        const float t  = Ts[i*16 + l];
        const float4 b = *reinterpret_cast<const float4*>(Bs + l*16 + jq*4);
        c0 = fmaf(t, b.x, c0); c1 = fmaf(t, b.y, c1);
        c2 = fmaf(t, b.z, c2); c3 = fmaf(t, b.w, c3);
    }
    return make_float4(c0, c1, c2, c3);
}

__device__ __forceinline__ void st4(float* dst, int i, int jq, float4 v) {
    *reinterpret_cast<float4*>(dst + i*16 + jq*4) = v;
}

// ---------------------------------------------------------------------------
// Kernel 1: 64 threads per matrix (2 matrices / 128-block).
// expm via Paterson-Stockmeyer Taylor-13 + scaling/squaring, then E, M, w, u.
// ---------------------------------------------------------------------------
__global__ void __launch_bounds__(128) prep_kernel(
    const float* __restrict__ mu_q,
    const float* __restrict__ sigma_q,
    const float* __restrict__ sigma_p,
    const float* __restrict__ phi,
    const float* __restrict__ gen,
    float* __restrict__ out_sigma)
{
    const int tid = threadIdx.x;
    const int mid = tid >> 6;          // matrix within block (0/1)
    const int t   = tid & 63;          // thread within matrix
    const int i   = t >> 2;            // row 0..15
    const int jq  = t & 3;             // col quad 0..3
    const int bn  = blockIdx.x * 2 + mid;

    __shared__ float sBuf[2][5 * 256]; // per matrix: bA,bX,bX2,bX3,bT
    __shared__ float sAux[2][52];      // r[16], mu[16], rmu[16], warp-norm[2]
    float* bA  = sBuf[mid];
    float* bX  = bA  + 256;
    float* bX2 = bX  + 256;
    float* bX3 = bX2 + 256;
    float* bT  = bX3 + 256;
    float* sr  = sAux[mid];
    float* smu = sAux[mid] + 16;
    float* srm = sAux[mid] + 32;
    float* snm = sAux[mid] + 48;

    // ---- A = phi . G (this thread's 4 elements) ----
    const float p0 = __ldg(&phi[bn*3 + 0]);
    const float p1 = __ldg(&phi[bn*3 + 1]);
    const float p2 = __ldg(&phi[bn*3 + 2]);

    float4 A;
    {
        const int base = i*16 + jq*4;
        const float4 g0 = *reinterpret_cast<const float4*>(gen + base);
        const float4 g1 = *reinterpret_cast<const float4*>(gen + 256 + base);
        const float4 g2 = *reinterpret_cast<const float4*>(gen + 512 + base);
        A.x = p0*g0.x + p1*g1.x + p2*g2.x;
        A.y = p0*g0.y + p1*g1.y + p2*g2.y;
        A.z = p0*g0.z + p1*g1.z + p2*g2.z;
        A.w = p0*g0.w + p1*g1.w + p2*g2.w;
    }

    if (t < 16) {
        const float mu = mu_q[bn*KK + t];
        const float sq = fmaxf(sigma_q[bn*KK + t], EPSV);
        const float sp = fmaxf(sigma_p[bn*KK + t], EPSV);
        const float r  = 1.0f / (sq + EPSV);
        sr[t]  = r;
        smu[t] = mu;
        srm[t] = r * mu;
        out_sigma[bn*KK + t] = ALPHA_C * 0.5f * (1.0f/sp - 1.0f/sq);
    }

    // ---- inf-norm: row sums over 4-lane groups, max over rows/warps ----
    float rs = fabsf(A.x) + fabsf(A.y) + fabsf(A.z) + fabsf(A.w);
    rs += __shfl_xor_sync(0xffffffffu, rs, 1);
    rs += __shfl_xor_sync(0xffffffffu, rs, 2);   // full row sum (all 4 lanes)
    rs = fmaxf(rs, __shfl_xor_sync(0xffffffffu, rs, 4));
    rs = fmaxf(rs, __shfl_xor_sync(0xffffffffu, rs, 8));
    rs = fmaxf(rs, __shfl_xor_sync(0xffffffffu, rs, 16)); // warp max (8 rows)
    if ((tid & 31) == 0) snm[(t >> 5) & 1] = rs;
    mbar(mid);
    float s = fmaxf(snm[0], snm[1]);

    int sc = 0;
    while (s > 2.0f && sc < 24) { s *= 0.5f; sc++; }
    const float scale = ldexpf(1.0f, -sc);
    A.x *= scale; A.y *= scale; A.z *= scale; A.w *= scale;

    // diag element of row i is at col i; owned if i in [jq*4, jq*4+4)
    const int  dq      = i - jq*4;
    const bool hasdiag = (dq >= 0) && (dq < 4);

    st4(bA, i, jq, A);
    mbar(mid);

    // ---- powers ----
    float4 X = mm4(bA, bA, i, jq);               // A^2
    st4(bX, i, jq, X);
    mbar(mid);
    float4 X2 = mm4(bX, bX, i, jq);              // A^4
    st4(bX2, i, jq, X2);
    mbar(mid);
    float4 X3 = mm4(bX2, bX, i, jq);             // A^6
    st4(bX3, i, jq, X3);

    // Taylor-13 even/odd coefficients
    const float c1c = 1.f/2.f,      c2c = 1.f/24.f,      c3c = 1.f/720.f;
    const float c4c = 1.f/40320.f,  c5c = 1.f/3628800.f, c6c = 1.f/479001600.f;
    const float d1c = 1.f/6.f,      d2c = 1.f/120.f,     d3c = 1.f/5040.f;
    const float d4c = 1.f/362880.f, d5c = 1.f/39916800.f, d6c = 1.6059044e-10f;

    // P bracket
    float4 tp;
    tp.x = fmaf(c4c, X.x, fmaf(c5c, X2.x, c6c*X3.x));
    tp.y = fmaf(c4c, X.y, fmaf(c5c, X2.y, c6c*X3.y));
    tp.z = fmaf(c4c, X.z, fmaf(c5c, X2.z, c6c*X3.z));
    tp.w = fmaf(c4c, X.w, fmaf(c5c, X2.w, c6c*X3.w));
    st4(bT, i, jq, tp);
    mbar(mid);                                    // bX3 + bT ready
    float4 Pb = mm4(bX3, bT, i, jq);
    float4 P;
    P.x = fmaf(c1c, X.x, fmaf(c2c, X2.x, fmaf(c3c, X3.x, Pb.x)));
    P.y = fmaf(c1c, X.y, fmaf(c2c, X2.y, fmaf(c3c, X3.y, Pb.y)));
    P.z = fmaf(c1c, X.z, fmaf(c2c, X2.z, fmaf(c3c, X3.z, Pb.z)));
    P.w = fmaf(c1c, X.w, fmaf(c2c, X2.w, fmaf(c3c, X3.w, Pb.w)));
    if (hasdiag) (&P.x)[dq] += 1.0f;

    // Q bracket
    float4 tq;
    tq.x = fmaf(d4c, X.x, fmaf(d5c, X2.x, d6c*X3.x));
    tq.y = fmaf(d4c, X.y, fmaf(d5c, X2.y, d6c*X3.y));
    tq.z = fmaf(d4c, X.z, fmaf(d5c, X2.z, d6c*X3.z));
    tq.w = fmaf(d4c, X.w, fmaf(d5c, X2.w, d6c*X3.w));
    mbar(mid);                                    // P-bracket reads of bT done
    st4(bT, i, jq, tq);
    mbar(mid);
    float4 Qb = mm4(bX3, bT, i, jq);
    float4 Q;
    Q.x = fmaf(d1c, X.x, fmaf(d2c, X2.x, fmaf(d3c, X3.x, Qb.x)));
    Q.y = fmaf(d1c, X.y, fmaf(d2c, X2.y, fmaf(d3c, X3.y, Qb.y)));
    Q.z = fmaf(d1c, X.z, fmaf(d2c, X2.z, fmaf(d3c, X3.z, Qb.z)));
    Q.w = fmaf(d1c, X.w, fmaf(d2c, X2.w, fmaf(d3c, X3.w, Qb.w)));
    if (hasdiag) (&Q.x)[dq] += 1.0f;

    mbar(mid);                                    // Q-bracket reads of bT done
    st4(bT, i, jq, Q);
    mbar(mid);
    float4 R = mm4(bA, bT, i, jq);                // A*Q
    R.x += P.x; R.y += P.y; R.z += P.z; R.w += P.w;

    // squarings (ping-pong bX / bX2; their old contents no longer needed)
    float* pp[2] = { bX, bX2 };
    int cur = 0;
    for (int q = 0; q < sc; q++) {
        mbar(mid);                                // prior reads of pp[cur] done
        st4(pp[cur], i, jq, R);
        mbar(mid);
        R = mm4(pp[cur], pp[cur], i, jq);
        cur ^= 1;
    }

    // ---- write E; stage E in bA for transposed access ----
    st4(g_E + (size_t)bn*256, i, jq, R);
    mbar(mid);                                    // readers of bA done (mm R / squarings)
    st4(bA, i, jq, R);
    mbar(mid);

    // ---- M[i][jq*4+q] = sum_l E[l][i] r[l] E[l][jq*4+q] ----
    {
        float a0=0.f, a1=0.f, a2=0.f, a3=0.f;
        #pragma unroll
        for (int l = 0; l < 16; l++) {
            const float e = bA[l*16 + i] * sr[l];
            const float4 b = *reinterpret_cast<const float4*>(bA + l*16 + jq*4);
            a0 = fmaf(e, b.x, a0); a1 = fmaf(e, b.y, a1);
            a2 = fmaf(e, b.z, a2); a3 = fmaf(e, b.w, a3);
        }
        st4(g_M + (size_t)bn*256, i, jq, make_float4(a0, a1, a2, a3));
    }

    // ---- w[k] = sum_l E[l][k] mu[l];  u[k] = sum_l E[l][k] r[l] mu[l] ----
    if (t < 16) {
        float wacc = 0.f, uacc = 0.f;
        #pragma unroll
        for (int l = 0; l < 16; l++) {
            const float e = bA[l*16 + t];
            wacc = fmaf(e, smu[l], wacc);
            uacc = fmaf(e, srm[l], uacc);
        }
        g_w[bn*KK + t] = wacc;
        g_u[bn*KK + t] = uacc;
    }
}

// ---------------------------------------------------------------------------
// Kernel 2 (phase A): partial j-sums. Grid (JSPLIT, NB/RPB), 256 threads =
// 16 groups of 16 lanes (one row each); 16 rows share the staged chunk.
// ---------------------------------------------------------------------------
__global__ void __launch_bounds__(256) pairA_kernel(
    const float* __restrict__ beta)
{
    __shared__ float sM[JCHUNK * 256];   // 16 KB
    __shared__ float swv[JCHUNK * 16];
    __shared__ float suv[JCHUNK * 16];

    const int tid   = threadIdx.x;
    const int g     = tid >> 4;
    const int lane  = tid & 15;
    const int split = blockIdx.x;
    const int bn    = blockIdx.y * RPB + g;
    const int b     = bn >> 7;
    const int irow  = bn & 127;
    const int j0    = split * JCHUNK;

    {
        const float4* src = reinterpret_cast<const float4*>(g_M + (size_t)(b*NN + j0) * 256);
        float4* dst = reinterpret_cast<float4*>(sM);
        #pragma unroll
        for (int q = 0; q < 4; q++) dst[q*256 + tid] = src[q*256 + tid];
        swv[tid] = g_w[(size_t)(b*NN + j0) * KK + tid];
        suv[tid] = g_u[(size_t)(b*NN + j0) * KK + tid];
    }

    float wir[16];
    {
        const float4* wp = reinterpret_cast<const float4*>(g_w + (size_t)bn * KK);
        #pragma unroll
        for (int q = 0; q < 4; q++) {
            const float4 v4 = wp[q];
            wir[q*4+0] = v4.x; wir[q*4+1] = v4.y; wir[q*4+2] = v4.z; wir[q*4+3] = v4.w;
        }
    }
    const float wi_self = g_w[(size_t)bn*KK + lane];
    const float* __restrict__ betarow = beta + (size_t)(b*NN + irow) * NN + j0;

    __syncthreads();

    float s1 = 0.f, s2 = 0.f, s3 = 0.f;

    #pragma unroll
    for (int jj = 0; jj < JCHUNK; jj++) {
        const float* __restrict__ Mc = sM + jj*256;   // symmetric
        float z0 = 0.f, z1 = 0.f;
        #pragma unroll
        for (int l = 0; l < 16; l += 2) {
            z0 = fmaf(Mc[ l     *16 + lane], wir[l    ], z0);
            z1 = fmaf(Mc[(l + 1)*16 + lane], wir[l + 1], z1);
        }
        const float y = (z0 + z1) - suv[jj*16 + lane];
        const float d = wi_self   - swv[jj*16 + lane];

        float tt = d * y;
        tt += __shfl_xor_sync(0xffffffffu, tt, 1);
        tt += __shfl_xor_sync(0xffffffffu, tt, 2);
        tt += __shfl_xor_sync(0xffffffffu, tt, 4);
        tt += __shfl_xor_sync(0xffffffffu, tt, 8);
        const float kl  = 0.5f * tt;
        const float bij = __ldg(betarow + jj);
        const float klb = kl * bij;

        s1 = fmaf(bij, y, s1);
        s2 = fmaf(klb, y, s2);
        s3 += klb;
    }

    const int idx = split * (NB*KK) + bn*KK + lane;
    g_s1[idx] = s1;
    g_s2[idx] = s2;
    if (lane == 0) g_s3[split * NB + bn] = s3;
}

// ---------------------------------------------------------------------------
// Kernel 3: combine splits, rotate by E_i, add self term.
// ---------------------------------------------------------------------------
__global__ void __launch_bounds__(256) finish_kernel(
    const float* __restrict__ mu_q,
    const float* __restrict__ mu_p,
    const float* __restrict__ sigma_p,
    float* __restrict__ out_mu)
{
    const int tid  = threadIdx.x;
    const int g    = tid >> 4;
    const int lane = tid & 15;
    const int bn   = blockIdx.x * 16 + g;

    float s1 = 0.f, s2 = 0.f, s3 = 0.f;
    #pragma unroll
    for (int s = 0; s < JSPLIT; s++) {
        s1 += g_s1[s*(NB*KK) + bn*KK + lane];
        s2 += g_s2[s*(NB*KK) + bn*KK + lane];
        s3 += g_s3[s*NB + bn];
    }
    const float v = LAM_C * s1 + (LAM_C / KAPPA_C) * (s2 - s3 * s1);

    float er[16];
    {
        const float4* ep = reinterpret_cast<const float4*>(g_E + (size_t)bn*256 + lane*16);
        #pragma unroll
        for (int q = 0; q < 4; q++) {
            const float4 t4 = ep[q];
            er[q*4+0] = t4.x; er[q*4+1] = t4.y; er[q*4+2] = t4.z; er[q*4+3] = t4.w;
        }
    }
    float o = 0.f;
    #pragma unroll
    for (int l = 0; l < 16; l++)
        o = fmaf(er[l], __shfl_sync(0xffffffffu, v, l, 16), o);

    const float sp   = fmaxf(sigma_p[bn*KK + lane], EPSV);
    const float self = ALPHA_C * (mu_q[bn*KK + lane] - mu_p[bn*KK + lane]) / sp;

    out_mu[bn*KK + lane] = self + o;
}

// ---------------------------------------------------------------------------
extern "C" void kernel_launch(void* const* d_in, const int* in_sizes, int n_in,
                              void* d_out, int out_size)
{
    const float* mu_q    = (const float*)d_in[0];
    const float* sigma_q = (const float*)d_in[1];
    const float* mu_p    = (const float*)d_in[2];
    const float* sigma_p = (const float*)d_in[3];
    const float* beta    = (const float*)d_in[4];
    const float* phi     = (const float*)d_in[5];
    const float* gen     = (const float*)d_in[6];

    float* out       = (float*)d_out;
    float* out_mu    = out;            // (B,N,K)
    float* out_sigma = out + NB*KK;    // (B,N,K)

    prep_kernel<<<NB/2, 128>>>(mu_q, sigma_q, sigma_p, phi, gen, out_sigma);
    pairA_kernel<<<dim3(JSPLIT, NB/RPB), 256>>>(beta);
    finish_kernel<<<NB/16, 256>>>(mu_q, mu_p, sigma_p, out_mu);
}